// round 2
// baseline (speedup 1.0000x reference)
#include <cuda_runtime.h>

#define NNODES 16384
#define HD 64
#define TLEN 12
#define NHEADS 8

// Persistent state (device globals: allocation-free scratch).
// g_h/g_c: [layer][head][node][HD]
__device__ float g_h[2 * 8 * NNODES * HD];
__device__ float g_c[2 * 8 * NNODES * HD];
// g_hs: final-layer hidden states, channel-major c = a*TLEN + t : [head][t][node][HD]
__device__ float g_hs[8 * TLEN * NNODES * HD];

__device__ __forceinline__ float sigf(float x) {
    return __fdividef(1.0f, 1.0f + __expf(-x));
}
__device__ __forceinline__ float tanh_fast(float x) {
    // accurate to ~1e-6; saturates correctly at +/-1 for large |x|
    return 2.0f * sigf(2.0f * x) - 1.0f;
}

// One LSTM step for one layer, all heads. Grid: (NNODES/64, NHEADS), 256 threads.
// CTA tile: 64 nodes x 256 gates, K = 128 (input 64 || h_prev 64).
// Thread (tx,ty): 8 nodes (4 f32x2 pairs) x 8 gate cols {g*64 + j*32 + tx}.
__global__ void __launch_bounds__(256, 2)
lstm_step_kernel(const float* __restrict__ x,
                 const float* __restrict__ Wih,
                 const float* __restrict__ Whh,
                 const float* __restrict__ bih,
                 const float* __restrict__ bhh,
                 const float* __restrict__ h0,
                 const float* __restrict__ c0,
                 int l, int t)
{
    __shared__ __align__(16) float As[32][66];   // [k][node], pad keeps 8B align + low conflict
    __shared__ __align__(16) float Bs[256][33];  // [gate][k], stride 33 -> conflict-free reads

    const int tid = threadIdx.x;
    const int tx  = tid & 31;
    const int ty  = tid >> 5;           // 0..7
    const int a   = blockIdx.y;
    const int tile = blockIdx.x * 64;

    const float* Wl  = Wih + (size_t)(l * 8 + a) * 256 * 64;
    const float* Whl = Whh + (size_t)(l * 8 + a) * 256 * 64;
    const float* bi  = bih + (l * 8 + a) * 256;
    const float* bh  = bhh + (l * 8 + a) * 256;

    const float* in_ptr = (l == 0) ? (x + (size_t)t * NNODES * HD)
                                   : (g_h + (size_t)a * NNODES * HD);          // layer0 h (current t)
    const float* hp_ptr = (t == 0) ? (h0 + (size_t)(a * 2 + l) * NNODES * HD)
                                   : (g_h + (size_t)(l * 8 + a) * NNODES * HD);
    const float* cp_ptr = (t == 0) ? (c0 + (size_t)(a * 2 + l) * NNODES * HD)
                                   : (g_c + (size_t)(l * 8 + a) * NNODES * HD);
    float* hout  = g_h + (size_t)(l * 8 + a) * NNODES * HD;
    float* cout_ = g_c + (size_t)(l * 8 + a) * NNODES * HD;
    float* hsout = g_hs + (size_t)(a * TLEN + t) * NNODES * HD;

    // Accumulators: packed pairs of nodes, init with bias (same bias both nodes).
    unsigned long long acc[4][8];
    #pragma unroll
    for (int g = 0; g < 4; g++)
        #pragma unroll
        for (int j = 0; j < 2; j++) {
            int col = g * 64 + j * 32 + tx;
            float b = bi[col] + bh[col];
            unsigned long long bb;
            asm("mov.b64 %0, {%1, %1};" : "=l"(bb) : "f"(b));
            #pragma unroll
            for (int p = 0; p < 4; p++) acc[p][g * 2 + j] = bb;
        }

    #pragma unroll
    for (int kc = 0; kc < 4; kc++) {
        const int k0 = kc * 32;
        const float* Asrc = (k0 < 64) ? in_ptr : hp_ptr;
        const float* Bsrc = (k0 < 64) ? Wl : Whl;
        const int dof = k0 & 63;

        // Stage A: 64 nodes x 32 k (transpose to [k][node])
        #pragma unroll
        for (int i = 0; i < 2; i++) {
            int idx = tid + i * 256;                 // 0..511
            int n = idx >> 3, k4 = (idx & 7) * 4;
            float4 v = *(const float4*)&Asrc[(size_t)(tile + n) * HD + dof + k4];
            As[k4 + 0][n] = v.x; As[k4 + 1][n] = v.y;
            As[k4 + 2][n] = v.z; As[k4 + 3][n] = v.w;
        }
        // Stage B: 256 gates x 32 k (natural [g][k])
        #pragma unroll
        for (int i = 0; i < 8; i++) {
            int idx = tid + i * 256;                 // 0..2047
            int g = idx >> 3, k4 = (idx & 7) * 4;
            float4 v = *(const float4*)&Bsrc[g * 64 + dof + k4];
            Bs[g][k4 + 0] = v.x; Bs[g][k4 + 1] = v.y;
            Bs[g][k4 + 2] = v.z; Bs[g][k4 + 3] = v.w;
        }
        __syncthreads();

        #pragma unroll
        for (int k = 0; k < 32; k++) {
            unsigned long long av[4];
            #pragma unroll
            for (int p = 0; p < 4; p++)
                av[p] = *(const unsigned long long*)&As[k][ty * 8 + 2 * p];
            #pragma unroll
            for (int g = 0; g < 4; g++)
                #pragma unroll
                for (int j = 0; j < 2; j++) {
                    float bv = Bs[g * 64 + j * 32 + tx][k];
                    unsigned long long bb;
                    asm("mov.b64 %0, {%1, %1};" : "=l"(bb) : "f"(bv));
                    const int s = g * 2 + j;
                    #pragma unroll
                    for (int p = 0; p < 4; p++)
                        asm("fma.rn.f32x2 %0, %1, %2, %0;"
                            : "+l"(acc[p][s]) : "l"(av[p]), "l"(bb));
                }
        }
        __syncthreads();
    }

    // Cell update: fully register-resident (gate cols chosen so each thread
    // owns i,f,g,o for units u = tx and tx+32 of its 8 nodes).
    #pragma unroll
    for (int p = 0; p < 4; p++) {
        float zlo[8], zhi[8];
        #pragma unroll
        for (int s = 0; s < 8; s++)
            asm("mov.b64 {%0, %1}, %2;" : "=f"(zlo[s]), "=f"(zhi[s]) : "l"(acc[p][s]));
        #pragma unroll
        for (int e = 0; e < 2; e++) {
            float zv[8];
            #pragma unroll
            for (int s = 0; s < 8; s++) zv[s] = e ? zhi[s] : zlo[s];
            const int n = tile + ty * 8 + 2 * p + e;
            #pragma unroll
            for (int j = 0; j < 2; j++) {
                const int u = j * 32 + tx;
                float zi = zv[0 + j], zf = zv[2 + j], zg = zv[4 + j], zo = zv[6 + j];
                float iv = sigf(zi);
                float fv = sigf(zf);
                float gv = tanh_fast(zg);
                float ov = sigf(zo);
                float cp = cp_ptr[(size_t)n * HD + u];
                float cn = fv * cp + iv * gv;
                float hn = ov * tanh_fast(cn);
                cout_[(size_t)n * HD + u] = cn;
                hout[(size_t)n * HD + u] = hn;
                if (l == 1) hsout[(size_t)n * HD + u] = hn;
            }
        }
    }
}

// out[o, n, u] = sum_c conv_w[o, c] * g_hs[c, n, u] + conv_b[o],  c = a*12+t (head-major)
__global__ void conv_kernel(const float* __restrict__ conv_w,
                            const float* __restrict__ conv_b,
                            float* __restrict__ out)
{
    __shared__ float ws[TLEN * 96];
    const int tid = threadIdx.x;
    for (int i = tid; i < TLEN * 96; i += 256) ws[i] = conv_w[i];
    __syncthreads();

    const size_t P = (size_t)NNODES * HD;                 // 1048576
    const size_t base = ((size_t)blockIdx.x * 256 + tid) * 4;

    float4 accv[TLEN];
    #pragma unroll
    for (int o = 0; o < TLEN; o++) {
        float b = conv_b[o];
        accv[o] = make_float4(b, b, b, b);
    }
    #pragma unroll 4
    for (int c = 0; c < 96; c++) {
        float4 v = *(const float4*)&g_hs[(size_t)c * P + base];
        #pragma unroll
        for (int o = 0; o < TLEN; o++) {
            float w = ws[o * 96 + c];
            accv[o].x += w * v.x; accv[o].y += w * v.y;
            accv[o].z += w * v.z; accv[o].w += w * v.w;
        }
    }
    #pragma unroll
    for (int o = 0; o < TLEN; o++)
        *(float4*)&out[(size_t)o * P + base] = accv[o];
}

extern "C" void kernel_launch(void* const* d_in, const int* in_sizes, int n_in,
                              void* d_out, int out_size)
{
    const float* x   = (const float*)d_in[0];
    const float* Wih = (const float*)d_in[1];
    const float* Whh = (const float*)d_in[2];
    const float* bih = (const float*)d_in[3];
    const float* bhh = (const float*)d_in[4];
    const float* h0  = (const float*)d_in[5];
    const float* c0  = (const float*)d_in[6];
    const float* cw  = (const float*)d_in[7];
    const float* cb  = (const float*)d_in[8];
    float* out = (float*)d_out;

    dim3 grid(NNODES / 64, NHEADS);
    for (int t = 0; t < TLEN; t++) {
        lstm_step_kernel<<<grid, 256>>>(x, Wih, Whh, bih, bhh, h0, c0, 0, t);
        lstm_step_kernel<<<grid, 256>>>(x, Wih, Whh, bih, bhh, h0, c0, 1, t);
    }
    conv_kernel<<<(NNODES * HD) / 1024, 256>>>(cw, cb, out);
}